// round 4
// baseline (speedup 1.0000x reference)
#include <cuda_runtime.h>
#include <cuda_bf16.h>

// B=64, N=1024, C=192, G=4
//   ori_g = clamp(x,0,r_g) ; q_g = rint(ori_g*255/r_g)*(r_g/255) (0 if r==0)
//   sw = softmax_g(alpha);  out = concat(sum_g ori_g*sw, sum_g q_g*sw)
//
// Setup kernel precomputes wo = sw and wq = sw*(r/255) tables once.
// Main kernel: scalar FMNMX clamp (alu pipe) + packed f32x2 FMA chain
// (fma pipe, 2 lanes/instr) + v2.b64 streaming stores.

#define C_DIM 192
#define G_DIM 4
#define C4    (C_DIM / 4)     // 48
#define TPB   192
#define NBLK  8192            // 8192 * 192 * 2 = 3,145,728 float4 = exact fit

typedef unsigned long long ull;

__device__ float g_wo[G_DIM][C_DIM];   // softmax weight
__device__ float g_wq[G_DIM][C_DIM];   // softmax weight * (r_g/255)
__device__ float g_scal[8];            // [0..3]=r_g, [4..7]=255/r_g (0 if r==0)

__global__ __launch_bounds__(TPB)
void qmod_setup_kernel(const float* __restrict__ r_in,
                       const float* __restrict__ alpha) {
    const int tid = threadIdx.x;
    float rg[G_DIM], bg[G_DIM];
#pragma unroll
    for (int g = 0; g < G_DIM; g++) {
        float r = r_in[g];
        rg[g] = r;
        bg[g] = r * (1.0f / 255.0f);
    }
    if (tid < 8) {
        int g = tid & 3;
        g_scal[tid] = (tid < 4) ? rg[g]
                                : ((rg[g] > 0.0f) ? (255.0f / rg[g]) : 0.0f);
    }
    // per-channel softmax over the 4 groups
    float a0 = alpha[0 * C_DIM + tid];
    float a1 = alpha[1 * C_DIM + tid];
    float a2 = alpha[2 * C_DIM + tid];
    float a3 = alpha[3 * C_DIM + tid];
    float m  = fmaxf(fmaxf(a0, a1), fmaxf(a2, a3));
    float e0 = expf(a0 - m);
    float e1 = expf(a1 - m);
    float e2 = expf(a2 - m);
    float e3 = expf(a3 - m);
    float inv_s = 1.0f / (e0 + e1 + e2 + e3);
    float w0 = e0 * inv_s, w1 = e1 * inv_s, w2 = e2 * inv_s, w3 = e3 * inv_s;
    g_wo[0][tid] = w0;  g_wq[0][tid] = w0 * bg[0];
    g_wo[1][tid] = w1;  g_wq[1][tid] = w1 * bg[1];
    g_wo[2][tid] = w2;  g_wq[2][tid] = w2 * bg[2];
    g_wo[3][tid] = w3;  g_wq[3][tid] = w3 * bg[3];
}

// ---- packed f32x2 helpers (Blackwell sm_103a) ----
__device__ __forceinline__ ull pk(float lo, float hi) {
    ull r; asm("mov.b64 %0, {%1, %2};" : "=l"(r) : "f"(lo), "f"(hi)); return r;
}
__device__ __forceinline__ ull fma2(ull a, ull b, ull c) {
    ull d; asm("fma.rn.f32x2 %0, %1, %2, %3;" : "=l"(d) : "l"(a), "l"(b), "l"(c)); return d;
}
__device__ __forceinline__ ull add2(ull a, ull b) {
    ull d; asm("add.rn.f32x2 %0, %1, %2;" : "=l"(d) : "l"(a), "l"(b)); return d;
}
__device__ __forceinline__ ull mul2(ull a, ull b) {
    ull d; asm("mul.rn.f32x2 %0, %1, %2;" : "=l"(d) : "l"(a), "l"(b)); return d;
}
__device__ __forceinline__ void st128cs(void* p, ull a, ull b) {
    asm volatile("st.global.cs.v2.b64 [%0], {%1, %2};"
                 :: "l"(p), "l"(a), "l"(b) : "memory");
}

__global__ __launch_bounds__(TPB)
void qmod_main_kernel(const float4* __restrict__ x,
                      float4* __restrict__ ori_out,
                      float4* __restrict__ q_out) {
    const int tid = threadIdx.x;
    const int c4  = tid % C4;          // fixed channel-quad for this thread
    const float MAGIC = 12582912.0f;   // 1.5 * 2^23

    // uniform group constants
    float rg[G_DIM];
    ull inv2[G_DIM];
#pragma unroll
    for (int g = 0; g < G_DIM; g++) {
        rg[g] = __ldg(&g_scal[g]);
        float iv = __ldg(&g_scal[4 + g]);
        inv2[g] = pk(iv, iv);
    }
    const ull M2  = pk(MAGIC, MAGIC);
    const ull nM2 = pk(-MAGIC, -MAGIC);

    // per-thread weight constants (L2-resident after first wave)
    ull wo2[G_DIM][2], wq2[G_DIM][2];
#pragma unroll
    for (int g = 0; g < G_DIM; g++) {
        float4 wo = __ldg(reinterpret_cast<const float4*>(g_wo[g]) + c4);
        float4 wq = __ldg(reinterpret_cast<const float4*>(g_wq[g]) + c4);
        wo2[g][0] = pk(wo.x, wo.y);  wo2[g][1] = pk(wo.z, wo.w);
        wq2[g][0] = pk(wq.x, wq.y);  wq2[g][1] = pk(wq.z, wq.w);
    }

    const int base = blockIdx.x * (2 * TPB) + tid;

    // front-batched streaming loads (MLP_p1 = 2)
    const float4 xa = __ldcs(&x[base]);
    const float4 xb = __ldcs(&x[base + TPB]);

#pragma unroll
    for (int e = 0; e < 2; e++) {
        const float4 xv = (e == 0) ? xa : xb;
        const int idx   = base + e * TPB;

        // shared ReLU (alu pipe)
        float rx0 = fmaxf(xv.x, 0.0f);
        float rx1 = fmaxf(xv.y, 0.0f);
        float rx2 = fmaxf(xv.z, 0.0f);
        float rx3 = fmaxf(xv.w, 0.0f);

        ull oacc01, oacc23, qacc01, qacc23;
#pragma unroll
        for (int g = 0; g < G_DIM; g++) {
            const float r = rg[g];
            float o0 = fminf(rx0, r);
            float o1 = fminf(rx1, r);
            float o2 = fminf(rx2, r);
            float o3 = fminf(rx3, r);
            ull o01 = pk(o0, o1);
            ull o23 = pk(o2, o3);
            // t = rint(o*inv) via magic-constant RNE (packed)
            ull t01 = add2(fma2(o01, inv2[g], M2), nM2);
            ull t23 = add2(fma2(o23, inv2[g], M2), nM2);
            if (g == 0) {
                oacc01 = mul2(o01, wo2[0][0]);
                oacc23 = mul2(o23, wo2[0][1]);
                qacc01 = mul2(t01, wq2[0][0]);
                qacc23 = mul2(t23, wq2[0][1]);
            } else {
                oacc01 = fma2(o01, wo2[g][0], oacc01);
                oacc23 = fma2(o23, wo2[g][1], oacc23);
                qacc01 = fma2(t01, wq2[g][0], qacc01);
                qacc23 = fma2(t23, wq2[g][1], qacc23);
            }
        }
        st128cs(&ori_out[idx], oacc01, oacc23);
        st128cs(&q_out[idx],   qacc01, qacc23);
    }
}

extern "C" void kernel_launch(void* const* d_in, const int* in_sizes, int n_in,
                              void* d_out, int out_size) {
    const float* x     = (const float*)d_in[0];   // inputs (64,1024,192)
    const float* r     = (const float*)d_in[1];   // groups_range1 (4,)
    const float* alpha = (const float*)d_in[2];   // alpha_activ (4,192)

    const int n_elem = in_sizes[0];               // 12,582,912
    const int n4     = n_elem / 4;                // 3,145,728

    float4* ori_out = (float4*)d_out;
    float4* q_out   = ori_out + n4;

    qmod_setup_kernel<<<1, TPB>>>(r, alpha);
    qmod_main_kernel<<<NBLK, TPB>>>((const float4*)x, ori_out, q_out);
}

// round 5
// speedup vs baseline: 1.0396x; 1.0396x over previous
#include <cuda_runtime.h>
#include <cuda_bf16.h>

// B=64, N=1024, C=192, G=4
//   ori_g = clamp(x,0,r_g) ; q_g = rint(ori_g*255/r_g)*(r_g/255) (0 if r==0)
//   sw = softmax_g(alpha);  out = concat(sum_g ori_g*sw, sum_g q_g*sw)
//
// Setup kernel precomputes wo = sw, wq = sw*(r/255) once; main kernel overlaps
// its launch + x-loads with setup via PDL (griddepcontrol), then runs a packed
// f32x2 FMA chain with ILP=4 front-batched loads.

#define C_DIM 192
#define G_DIM 4
#define C4    (C_DIM / 4)     // 48
#define TPB   192
#define ILP   4
#define NBLK  4096            // 4096 * 192 * 4 = 3,145,728 float4 = exact fit

typedef unsigned long long ull;

__device__ float g_wo[G_DIM][C_DIM];   // softmax weight
__device__ float g_wq[G_DIM][C_DIM];   // softmax weight * (r_g/255)
__device__ float g_scal[8];            // [0..3]=r_g, [4..7]=255/r_g (0 if r==0)

__global__ __launch_bounds__(TPB)
void qmod_setup_kernel(const float* __restrict__ r_in,
                       const float* __restrict__ alpha) {
    const int tid = threadIdx.x;
    float rg[G_DIM], bg[G_DIM];
#pragma unroll
    for (int g = 0; g < G_DIM; g++) {
        float r = r_in[g];
        rg[g] = r;
        bg[g] = r * (1.0f / 255.0f);
    }
    if (tid < 8) {
        int g = tid & 3;
        g_scal[tid] = (tid < 4) ? rg[g]
                                : ((rg[g] > 0.0f) ? (255.0f / rg[g]) : 0.0f);
    }
    // per-channel softmax over the 4 groups (TPB == C_DIM)
    float a0 = alpha[0 * C_DIM + tid];
    float a1 = alpha[1 * C_DIM + tid];
    float a2 = alpha[2 * C_DIM + tid];
    float a3 = alpha[3 * C_DIM + tid];
    float m  = fmaxf(fmaxf(a0, a1), fmaxf(a2, a3));
    float e0 = expf(a0 - m);
    float e1 = expf(a1 - m);
    float e2 = expf(a2 - m);
    float e3 = expf(a3 - m);
    float inv_s = 1.0f / (e0 + e1 + e2 + e3);
    float w0 = e0 * inv_s, w1 = e1 * inv_s, w2 = e2 * inv_s, w3 = e3 * inv_s;
    g_wo[0][tid] = w0;  g_wq[0][tid] = w0 * bg[0];
    g_wo[1][tid] = w1;  g_wq[1][tid] = w1 * bg[1];
    g_wo[2][tid] = w2;  g_wq[2][tid] = w2 * bg[2];
    g_wo[3][tid] = w3;  g_wq[3][tid] = w3 * bg[3];

    // make table writes visible, then let the dependent grid start
    __threadfence();
    __syncthreads();
    if (tid == 0) {
        asm volatile("griddepcontrol.launch_dependents;");
    }
}

// ---- packed f32x2 helpers (Blackwell sm_103a) ----
__device__ __forceinline__ ull pk(float lo, float hi) {
    ull r; asm("mov.b64 %0, {%1, %2};" : "=l"(r) : "f"(lo), "f"(hi)); return r;
}
__device__ __forceinline__ ull fma2(ull a, ull b, ull c) {
    ull d; asm("fma.rn.f32x2 %0, %1, %2, %3;" : "=l"(d) : "l"(a), "l"(b), "l"(c)); return d;
}
__device__ __forceinline__ ull add2(ull a, ull b) {
    ull d; asm("add.rn.f32x2 %0, %1, %2;" : "=l"(d) : "l"(a), "l"(b)); return d;
}
__device__ __forceinline__ ull mul2(ull a, ull b) {
    ull d; asm("mul.rn.f32x2 %0, %1, %2;" : "=l"(d) : "l"(a), "l"(b)); return d;
}
__device__ __forceinline__ void st128cs(void* p, ull a, ull b) {
    asm volatile("st.global.cs.v2.b64 [%0], {%1, %2};"
                 :: "l"(p), "l"(a), "l"(b) : "memory");
}

__global__ __launch_bounds__(TPB)
void qmod_main_kernel(const float4* __restrict__ x,
                      float4* __restrict__ ori_out,
                      float4* __restrict__ q_out) {
    const int tid = threadIdx.x;
    const int c4  = tid % C4;          // fixed channel-quad for this thread
    const float MAGIC = 12582912.0f;   // 1.5 * 2^23

    const int base = blockIdx.x * (ILP * TPB) + tid;

    // front-batched streaming loads — independent of setup kernel, issue
    // BEFORE the grid-dependency wait so they overlap setup execution.
    float4 xv[ILP];
#pragma unroll
    for (int k = 0; k < ILP; k++) xv[k] = __ldcs(&x[base + k * TPB]);

    // gate only the weight-table reads on setup completion
    asm volatile("griddepcontrol.wait;");

    float rg[G_DIM];
    ull inv2[G_DIM];
#pragma unroll
    for (int g = 0; g < G_DIM; g++) {
        rg[g] = __ldg(&g_scal[g]);
        float iv = __ldg(&g_scal[4 + g]);
        inv2[g] = pk(iv, iv);
    }
    const ull M2  = pk(MAGIC, MAGIC);
    const ull nM2 = pk(-MAGIC, -MAGIC);

    ull wo2[G_DIM][2], wq2[G_DIM][2];
#pragma unroll
    for (int g = 0; g < G_DIM; g++) {
        float4 wo = __ldg(reinterpret_cast<const float4*>(g_wo[g]) + c4);
        float4 wq = __ldg(reinterpret_cast<const float4*>(g_wq[g]) + c4);
        wo2[g][0] = pk(wo.x, wo.y);  wo2[g][1] = pk(wo.z, wo.w);
        wq2[g][0] = pk(wq.x, wq.y);  wq2[g][1] = pk(wq.z, wq.w);
    }

#pragma unroll
    for (int e = 0; e < ILP; e++) {
        const int idx = base + e * TPB;

        // shared ReLU (alu pipe)
        float rx0 = fmaxf(xv[e].x, 0.0f);
        float rx1 = fmaxf(xv[e].y, 0.0f);
        float rx2 = fmaxf(xv[e].z, 0.0f);
        float rx3 = fmaxf(xv[e].w, 0.0f);

        ull oacc01, oacc23, qacc01, qacc23;
#pragma unroll
        for (int g = 0; g < G_DIM; g++) {
            const float r = rg[g];
            float o0 = fminf(rx0, r);
            float o1 = fminf(rx1, r);
            float o2 = fminf(rx2, r);
            float o3 = fminf(rx3, r);
            ull o01 = pk(o0, o1);
            ull o23 = pk(o2, o3);
            // t = rint(o*inv) via magic-constant RNE (packed; o*inv in [0,255])
            ull t01 = add2(fma2(o01, inv2[g], M2), nM2);
            ull t23 = add2(fma2(o23, inv2[g], M2), nM2);
            if (g == 0) {
                oacc01 = mul2(o01, wo2[0][0]);
                oacc23 = mul2(o23, wo2[0][1]);
                qacc01 = mul2(t01, wq2[0][0]);
                qacc23 = mul2(t23, wq2[0][1]);
            } else {
                oacc01 = fma2(o01, wo2[g][0], oacc01);
                oacc23 = fma2(o23, wo2[g][1], oacc23);
                qacc01 = fma2(t01, wq2[g][0], qacc01);
                qacc23 = fma2(t23, wq2[g][1], qacc23);
            }
        }
        st128cs(&ori_out[idx], oacc01, oacc23);
        st128cs(&q_out[idx],   qacc01, qacc23);
    }
}

extern "C" void kernel_launch(void* const* d_in, const int* in_sizes, int n_in,
                              void* d_out, int out_size) {
    const float* x     = (const float*)d_in[0];   // inputs (64,1024,192)
    const float* r     = (const float*)d_in[1];   // groups_range1 (4,)
    const float* alpha = (const float*)d_in[2];   // alpha_activ (4,192)

    const int n_elem = in_sizes[0];               // 12,582,912
    const int n4     = n_elem / 4;                // 3,145,728

    float4* ori_out = (float4*)d_out;
    float4* q_out   = ori_out + n4;

    qmod_setup_kernel<<<1, TPB>>>(r, alpha);

    // main kernel launched with Programmatic Stream Serialization: it may
    // begin (issuing its x loads) while setup is still running; the
    // griddepcontrol.wait inside gates the weight-table reads.
    cudaLaunchConfig_t cfg = {};
    cfg.gridDim  = dim3(NBLK, 1, 1);
    cfg.blockDim = dim3(TPB, 1, 1);
    cfg.dynamicSmemBytes = 0;
    cudaLaunchAttribute attrs[1];
    attrs[0].id = cudaLaunchAttributeProgrammaticStreamSerialization;
    attrs[0].val.programmaticStreamSerializationAllowed = 1;
    cfg.attrs    = attrs;
    cfg.numAttrs = 1;
    cudaLaunchKernelEx(&cfg, qmod_main_kernel,
                       (const float4*)x, ori_out, q_out);
}

// round 6
// speedup vs baseline: 1.1156x; 1.0731x over previous
#include <cuda_runtime.h>
#include <cuda_bf16.h>

// B=64, N=1024, C=192, G=4
//   ori_g = clamp(x,0,r_g) ; q_g = rint(ori_g*255/r_g)*(r_g/255) (0 if r==0)
//   sw = softmax_g(alpha);  out = concat(sum_g ori_g*sw, sum_g q_g*sw)
//
// Single kernel. Each block: issue 8 x-loads FIRST, then compute the tiny
// per-channel softmax prologue (hidden under the in-flight DRAM loads),
// then packed-f32x2 math + streaming 128-bit stores.
// TPB=192: both block stride (8*192) and lane stride (192) are divisible by
// C4=48, so each thread's channel quad is fixed -> weights live in registers.

#define C_DIM 192
#define G_DIM 4
#define C4    (C_DIM / 4)     // 48
#define TPB   192
#define ILP   8
#define NBLK  2048            // 2048 * 192 * 8 = 3,145,728 float4 = exact fit

typedef unsigned long long ull;

// ---- packed f32x2 helpers (Blackwell sm_103a) ----
__device__ __forceinline__ ull pk(float lo, float hi) {
    ull r; asm("mov.b64 %0, {%1, %2};" : "=l"(r) : "f"(lo), "f"(hi)); return r;
}
__device__ __forceinline__ ull fma2(ull a, ull b, ull c) {
    ull d; asm("fma.rn.f32x2 %0, %1, %2, %3;" : "=l"(d) : "l"(a), "l"(b), "l"(c)); return d;
}
__device__ __forceinline__ ull add2(ull a, ull b) {
    ull d; asm("add.rn.f32x2 %0, %1, %2;" : "=l"(d) : "l"(a), "l"(b)); return d;
}
__device__ __forceinline__ ull mul2(ull a, ull b) {
    ull d; asm("mul.rn.f32x2 %0, %1, %2;" : "=l"(d) : "l"(a), "l"(b)); return d;
}
__device__ __forceinline__ void st128cs(void* p, ull a, ull b) {
    asm volatile("st.global.cs.v2.b64 [%0], {%1, %2};"
                 :: "l"(p), "l"(a), "l"(b) : "memory");
}

__global__ __launch_bounds__(TPB)
void qmod_fused_kernel(const float4* __restrict__ x,
                       const float*  __restrict__ r_in,
                       const float*  __restrict__ alpha,
                       float4* __restrict__ ori_out,
                       float4* __restrict__ q_out) {
    __shared__ float sw_o[G_DIM][C_DIM];
    __shared__ float sw_q[G_DIM][C_DIM];

    const int tid = threadIdx.x;
    const float MAGIC = 12582912.0f;   // 1.5 * 2^23 : RNE rounding constant

    const int base = blockIdx.x * (ILP * TPB) + tid;

    // ---- issue all data loads FIRST; prologue hides under their latency ----
    float4 xv[ILP];
#pragma unroll
    for (int k = 0; k < ILP; k++) xv[k] = __ldcs(&x[base + k * TPB]);

    // ---- per-block prologue (alpha/r are L2-hot after the first wave) ----
    float rg[G_DIM], bg[G_DIM];
#pragma unroll
    for (int g = 0; g < G_DIM; g++) {
        float r = __ldg(&r_in[g]);
        rg[g] = r;
        bg[g] = r * (1.0f / 255.0f);
    }
    {
        float a0 = __ldg(&alpha[0 * C_DIM + tid]);
        float a1 = __ldg(&alpha[1 * C_DIM + tid]);
        float a2 = __ldg(&alpha[2 * C_DIM + tid]);
        float a3 = __ldg(&alpha[3 * C_DIM + tid]);
        float m  = fmaxf(fmaxf(a0, a1), fmaxf(a2, a3));
        float e0 = expf(a0 - m);
        float e1 = expf(a1 - m);
        float e2 = expf(a2 - m);
        float e3 = expf(a3 - m);
        float inv_s = 1.0f / (e0 + e1 + e2 + e3);
        float w0 = e0 * inv_s, w1 = e1 * inv_s, w2 = e2 * inv_s, w3 = e3 * inv_s;
        sw_o[0][tid] = w0;  sw_q[0][tid] = w0 * bg[0];
        sw_o[1][tid] = w1;  sw_q[1][tid] = w1 * bg[1];
        sw_o[2][tid] = w2;  sw_q[2][tid] = w2 * bg[2];
        sw_o[3][tid] = w3;  sw_q[3][tid] = w3 * bg[3];
    }
    __syncthreads();   // does not drain the in-flight LDGs

    // channel-quad-invariant weights -> packed registers
    const int c4 = tid % C4;
    ull inv2[G_DIM], wo2[G_DIM][2], wq2[G_DIM][2];
#pragma unroll
    for (int g = 0; g < G_DIM; g++) {
        float iv = (rg[g] > 0.0f) ? (255.0f / rg[g]) : 0.0f;
        inv2[g] = pk(iv, iv);
        float4 wo = reinterpret_cast<const float4*>(sw_o[g])[c4];
        float4 wq = reinterpret_cast<const float4*>(sw_q[g])[c4];
        wo2[g][0] = pk(wo.x, wo.y);  wo2[g][1] = pk(wo.z, wo.w);
        wq2[g][0] = pk(wq.x, wq.y);  wq2[g][1] = pk(wq.z, wq.w);
    }
    const ull M2  = pk(MAGIC, MAGIC);
    const ull nM2 = pk(-MAGIC, -MAGIC);

#pragma unroll
    for (int e = 0; e < ILP; e++) {
        const int idx = base + e * TPB;

        // shared ReLU (alu pipe)
        float rx0 = fmaxf(xv[e].x, 0.0f);
        float rx1 = fmaxf(xv[e].y, 0.0f);
        float rx2 = fmaxf(xv[e].z, 0.0f);
        float rx3 = fmaxf(xv[e].w, 0.0f);

        ull oacc01, oacc23, qacc01, qacc23;
#pragma unroll
        for (int g = 0; g < G_DIM; g++) {
            const float r = rg[g];
            float o0 = fminf(rx0, r);
            float o1 = fminf(rx1, r);
            float o2 = fminf(rx2, r);
            float o3 = fminf(rx3, r);
            ull o01 = pk(o0, o1);
            ull o23 = pk(o2, o3);
            // t = rint(o*inv) via magic-constant RNE (packed; o*inv in [0,255])
            ull t01 = add2(fma2(o01, inv2[g], M2), nM2);
            ull t23 = add2(fma2(o23, inv2[g], M2), nM2);
            if (g == 0) {
                oacc01 = mul2(o01, wo2[0][0]);
                oacc23 = mul2(o23, wo2[0][1]);
                qacc01 = mul2(t01, wq2[0][0]);
                qacc23 = mul2(t23, wq2[0][1]);
            } else {
                oacc01 = fma2(o01, wo2[g][0], oacc01);
                oacc23 = fma2(o23, wo2[g][1], oacc23);
                qacc01 = fma2(t01, wq2[g][0], qacc01);
                qacc23 = fma2(t23, wq2[g][1], qacc23);
            }
        }
        st128cs(&ori_out[idx], oacc01, oacc23);
        st128cs(&q_out[idx],   qacc01, qacc23);
    }
}

extern "C" void kernel_launch(void* const* d_in, const int* in_sizes, int n_in,
                              void* d_out, int out_size) {
    const float* x     = (const float*)d_in[0];   // inputs (64,1024,192)
    const float* r     = (const float*)d_in[1];   // groups_range1 (4,)
    const float* alpha = (const float*)d_in[2];   // alpha_activ (4,192)

    const int n_elem = in_sizes[0];               // 12,582,912
    const int n4     = n_elem / 4;                // 3,145,728

    float4* ori_out = (float4*)d_out;
    float4* q_out   = ori_out + n4;

    qmod_fused_kernel<<<NBLK, TPB>>>((const float4*)x, r, alpha,
                                     ori_out, q_out);
}